// round 7
// baseline (speedup 1.0000x reference)
#include <cuda_runtime.h>
#include <cuda_bf16.h>
#include <cfloat>
#include <math.h>

// Problem constants
#define B_  64
#define C_  256
#define N_  20000
#define NT_ 64
#define K_  8
#define ROWS_ (B_ * K_ * NT_)   // 32768 output token rows
#define NBLK_ 157               // ceil(20000/128) sims blocks
#define NCAND_ (NBLK_ * 8)      // 1256 candidates per row

// Scratch (device globals; no allocation allowed)
__device__ int      g_top_idx[B_ * K_];
__device__ unsigned g_w_tf32[C_ * C_];
__device__ float    g_cand_v[B_ * NCAND_];
__device__ int      g_cand_i[B_ * NCAND_];

__device__ __forceinline__ unsigned f2tf32(float f) {
    unsigned u;
    asm("cvt.rna.tf32.f32 %0, %1;" : "=r"(u) : "f"(f));
    return u;
}

__device__ __forceinline__ void mma_tf32(float* d, const unsigned* a, const unsigned* b) {
    asm volatile(
        "mma.sync.aligned.m16n8k8.row.col.f32.tf32.tf32.f32 "
        "{%0,%1,%2,%3}, {%4,%5,%6,%7}, {%8,%9}, {%0,%1,%2,%3};"
        : "+f"(d[0]), "+f"(d[1]), "+f"(d[2]), "+f"(d[3])
        : "r"(a[0]), "r"(a[1]), "r"(a[2]), "r"(a[3]),
          "r"(b[0]), "r"(b[1]));
}

__device__ __forceinline__ void cp_async16(void* smem_dst, const void* gsrc) {
    unsigned saddr = (unsigned)__cvta_generic_to_shared(smem_dst);
    asm volatile("cp.async.cg.shared.global [%0], [%1], 16;\n"
                 :: "r"(saddr), "l"(gsrc));
}
__device__ __forceinline__ void cp_commit() {
    asm volatile("cp.async.commit_group;\n" ::: "memory");
}
__device__ __forceinline__ void cp_wait_all() {
    asm volatile("cp.async.wait_group 0;\n" ::: "memory");
}

// ---------------------------------------------------------------------------
// Kernel 1 (fused): blocks [0, NBLK_): sims via compensated tf32 MMA with
// fused summary-norms AND fused per-block top-8 candidate extraction.
// Blocks [NBLK_, NBLK_+64): convert W to tf32 bits (independent work).
// ---------------------------------------------------------------------------
__global__ void __launch_bounds__(256) sims_topk_wcvt(const float* __restrict__ q,
                                                      const float* __restrict__ s,
                                                      const float* __restrict__ W) {
    // ---- W-convert blocks ----
    if (blockIdx.x >= NBLK_) {
        int i = (blockIdx.x - NBLK_) * 256 + threadIdx.x;   // 16384 float4s
        float4 v = ((const float4*)W)[i];
        ((uint4*)g_w_tf32)[i] =
            make_uint4(f2tf32(v.x), f2tf32(v.y), f2tf32(v.z), f2tf32(v.w));
        return;
    }

    extern __shared__ unsigned dsm[];
    unsigned* Qh = dsm;            // 64*36
    unsigned* Ql = dsm + 2304;     // 64*36
    unsigned* Sh = dsm + 4608;     // 128*36
    unsigned* Sl = dsm + 9216;     // 128*36
    float* sinv  = (float*)dsm;    // [128], reused after k-loop (over Qh)
    float* V     = (float*)(dsm + 4608);   // [64][136] sims tile (over Sh/Sl)

    int tid  = threadIdx.x;
    int lane = tid & 31;
    int w    = tid >> 5;
    int lr   = lane >> 2;
    int lc   = lane & 3;
    int n0   = blockIdx.x * 128;

    float acc[4][2][4];
#pragma unroll
    for (int mt = 0; mt < 4; mt++)
#pragma unroll
        for (int nt = 0; nt < 2; nt++)
#pragma unroll
            for (int r = 0; r < 4; r++) acc[mt][nt][r] = 0.f;

    float ssq[4] = {0.f, 0.f, 0.f, 0.f};

    for (int k0 = 0; k0 < C_; k0 += 32) {
        // stage Q hi/lo: 64x32 = 512 float4
#pragma unroll
        for (int i = 0; i < 2; i++) {
            int idx = tid + 256 * i;
            int r = idx >> 3, qv = idx & 7;
            float4 v = *(const float4*)(q + (size_t)r * C_ + k0 + qv * 4);
            unsigned hx = f2tf32(v.x), hy = f2tf32(v.y), hz = f2tf32(v.z), hw = f2tf32(v.w);
            *(uint4*)(Qh + r * 36 + qv * 4) = make_uint4(hx, hy, hz, hw);
            *(uint4*)(Ql + r * 36 + qv * 4) = make_uint4(
                f2tf32(v.x - __uint_as_float(hx)), f2tf32(v.y - __uint_as_float(hy)),
                f2tf32(v.z - __uint_as_float(hz)), f2tf32(v.w - __uint_as_float(hw)));
        }
        // stage S hi/lo: 128x32 = 1024 float4; accumulate per-row sumsq
#pragma unroll
        for (int i = 0; i < 4; i++) {
            int idx = tid + 256 * i;
            int r = idx >> 3, qv = idx & 7;
            int n = n0 + r;
            float4 v = make_float4(0.f, 0.f, 0.f, 0.f);
            if (n < N_) v = *(const float4*)(s + (size_t)n * C_ + k0 + qv * 4);
            ssq[i] += v.x * v.x + v.y * v.y + v.z * v.z + v.w * v.w;
            unsigned hx = f2tf32(v.x), hy = f2tf32(v.y), hz = f2tf32(v.z), hw = f2tf32(v.w);
            *(uint4*)(Sh + r * 36 + qv * 4) = make_uint4(hx, hy, hz, hw);
            *(uint4*)(Sl + r * 36 + qv * 4) = make_uint4(
                f2tf32(v.x - __uint_as_float(hx)), f2tf32(v.y - __uint_as_float(hy)),
                f2tf32(v.z - __uint_as_float(hz)), f2tf32(v.w - __uint_as_float(hw)));
        }
        __syncthreads();
#pragma unroll
        for (int ks = 0; ks < 4; ks++) {
            int k = ks * 8;
            unsigned ah[4][4], al[4][4], bh[2][2], bl[2][2];
#pragma unroll
            for (int mt = 0; mt < 4; mt++) {
                int r = mt * 16 + lr;
                ah[mt][0] = Qh[r * 36 + k + lc];
                ah[mt][1] = Qh[(r + 8) * 36 + k + lc];
                ah[mt][2] = Qh[r * 36 + k + lc + 4];
                ah[mt][3] = Qh[(r + 8) * 36 + k + lc + 4];
                al[mt][0] = Ql[r * 36 + k + lc];
                al[mt][1] = Ql[(r + 8) * 36 + k + lc];
                al[mt][2] = Ql[r * 36 + k + lc + 4];
                al[mt][3] = Ql[(r + 8) * 36 + k + lc + 4];
            }
#pragma unroll
            for (int nt = 0; nt < 2; nt++) {
                int c = w * 16 + nt * 8 + lr;
                bh[nt][0] = Sh[c * 36 + k + lc];
                bh[nt][1] = Sh[c * 36 + k + lc + 4];
                bl[nt][0] = Sl[c * 36 + k + lc];
                bl[nt][1] = Sl[c * 36 + k + lc + 4];
            }
#pragma unroll
            for (int mt = 0; mt < 4; mt++)
#pragma unroll
                for (int nt = 0; nt < 2; nt++) {
                    mma_tf32(acc[mt][nt], ah[mt], bh[nt]);
                    mma_tf32(acc[mt][nt], ah[mt], bl[nt]);
                    mma_tf32(acc[mt][nt], al[mt], bh[nt]);
                }
        }
        __syncthreads();
    }

    // finalize per-column inverse norms (reduce ssq across 8 staging threads)
#pragma unroll
    for (int i = 0; i < 4; i++) {
#pragma unroll
        for (int off = 1; off <= 4; off <<= 1)
            ssq[i] += __shfl_xor_sync(0xffffffffu, ssq[i], off);
        if ((tid & 7) == 0) {
            int r = (tid + 256 * i) >> 3;
            sinv[r] = 1.0f / fmaxf(sqrtf(ssq[i]), 1e-12f);
        }
    }
    __syncthreads();

    // scale + spill sims tile to smem V[64][136]
#pragma unroll
    for (int mt = 0; mt < 4; mt++) {
        int r0 = mt * 16 + lr;     // b index (0..63)
#pragma unroll
        for (int nt = 0; nt < 2; nt++) {
            int cl = w * 16 + nt * 8 + 2 * lc;
            bool valid = (n0 + cl) < N_;
            float i0 = valid ? sinv[cl]     : 0.f;
            float i1 = valid ? sinv[cl + 1] : 0.f;
            float2 v0, v1;
            v0.x = valid ? acc[mt][nt][0] * i0 : -FLT_MAX;
            v0.y = valid ? acc[mt][nt][1] * i1 : -FLT_MAX;
            v1.x = valid ? acc[mt][nt][2] * i0 : -FLT_MAX;
            v1.y = valid ? acc[mt][nt][3] * i1 : -FLT_MAX;
            *(float2*)(V + r0 * 136 + cl)       = v0;
            *(float2*)(V + (r0 + 8) * 136 + cl) = v1;
        }
    }
    __syncthreads();

    // per-row top-8 within this block's 128 columns; warp w -> rows w*8..w*8+7
#pragma unroll 1
    for (int rr = 0; rr < 8; rr++) {
        int row = w * 8 + rr;
        float4 vv = *(const float4*)(V + row * 136 + lane * 4);
        float v[4] = {vv.x, vv.y, vv.z, vv.w};
        int base = n0 + lane * 4;
#pragma unroll 1
        for (int round = 0; round < 8; round++) {
            // local best among remaining (value desc, index asc == slot asc)
            float bv = v[0]; int bj = 0;
#pragma unroll
            for (int j = 1; j < 4; j++)
                if (v[j] > bv) { bv = v[j]; bj = j; }
            int bi = base + bj;
            int bs = (lane << 2) + bj;
            // butterfly across warp
#pragma unroll
            for (int off = 16; off > 0; off >>= 1) {
                float ov = __shfl_xor_sync(0xffffffffu, bv, off);
                int   oi = __shfl_xor_sync(0xffffffffu, bi, off);
                int   os = __shfl_xor_sync(0xffffffffu, bs, off);
                if (ov > bv || (ov == bv && oi < bi)) { bv = ov; bi = oi; bs = os; }
            }
            if (lane == 0) {
                g_cand_v[(size_t)row * NCAND_ + blockIdx.x * 8 + round] = bv;
                g_cand_i[(size_t)row * NCAND_ + blockIdx.x * 8 + round] = bi;
            }
            if ((bs >> 2) == lane) v[bs & 3] = -FLT_MAX;
        }
    }
}

// ---------------------------------------------------------------------------
// Kernel 2: reduce NCAND_ candidates/row -> top-8. One block (256t) per row.
// ---------------------------------------------------------------------------
__global__ void __launch_bounds__(256) topk_stage2() {
    __shared__ float sv[2048];
    __shared__ int   si[2048];
    __shared__ float wv[8];
    __shared__ int   wi[8];
    __shared__ int   wsl[8];

    int row  = blockIdx.x;
    int tid  = threadIdx.x;
    int lane = tid & 31;
    int w    = tid >> 5;
    const float* cv = g_cand_v + (size_t)row * NCAND_;
    const int*   ci = g_cand_i + (size_t)row * NCAND_;

    float tv[8];
    int   ti[8];
#pragma unroll
    for (int p = 0; p < 8; p++) { tv[p] = -FLT_MAX; ti[p] = 0x7fffffff; }

    for (int n = tid; n < NCAND_; n += 256) {
        float v = cv[n];
        int  idx = ci[n];
        if (v > tv[7] || (v == tv[7] && idx < ti[7])) {
            tv[7] = v; ti[7] = idx;
#pragma unroll
            for (int p = 7; p >= 1; p--) {
                bool sw = (tv[p] > tv[p - 1]) ||
                          (tv[p] == tv[p - 1] && ti[p] < ti[p - 1]);
                if (sw) {
                    float fv = tv[p]; tv[p] = tv[p - 1]; tv[p - 1] = fv;
                    int   fi = ti[p]; ti[p] = ti[p - 1]; ti[p - 1] = fi;
                }
            }
        }
    }
#pragma unroll
    for (int p = 0; p < 8; p++) { sv[tid * 8 + p] = tv[p]; si[tid * 8 + p] = ti[p]; }
    __syncthreads();

    for (int round = 0; round < 8; round++) {
        float bv = -FLT_MAX; int bi = 0x7fffffff; int bs = 0;
#pragma unroll
        for (int p = 0; p < 8; p++) {
            float v = sv[tid * 8 + p];
            int idx = si[tid * 8 + p];
            if (v > bv || (v == bv && idx < bi)) { bv = v; bi = idx; bs = tid * 8 + p; }
        }
#pragma unroll
        for (int off = 16; off > 0; off >>= 1) {
            float ov = __shfl_xor_sync(0xffffffffu, bv, off);
            int   oi = __shfl_xor_sync(0xffffffffu, bi, off);
            int   os = __shfl_xor_sync(0xffffffffu, bs, off);
            if (ov > bv || (ov == bv && oi < bi)) { bv = ov; bi = oi; bs = os; }
        }
        if (lane == 0) { wv[w] = bv; wi[w] = bi; wsl[w] = bs; }
        __syncthreads();
        if (tid == 0) {
            float Bv = wv[0]; int Bi = wi[0]; int Bs = wsl[0];
#pragma unroll
            for (int j = 1; j < 8; j++) {
                if (wv[j] > Bv || (wv[j] == Bv && wi[j] < Bi)) {
                    Bv = wv[j]; Bi = wi[j]; Bs = wsl[j];
                }
            }
            g_top_idx[row * K_ + round] = Bi;
            sv[Bs] = -FLT_MAX;
        }
        __syncthreads();
    }
}

// ---------------------------------------------------------------------------
// Kernel 3: gathered GEMM via tf32 mma.sync with cp.async double buffering,
// fused bias + LayerNorm + gate. Block: 64 rows x 256 cols, 256 threads.
// ---------------------------------------------------------------------------
__global__ void __launch_bounds__(256, 2)
gemm_ln_tc(const float* __restrict__ templates,
           const float* __restrict__ bias,
           const float* __restrict__ gamma,
           const float* __restrict__ beta,
           const float* __restrict__ gate_logit,
           float* __restrict__ out) {
    extern __shared__ unsigned dsm[];
    unsigned* Ws0 = dsm;              // 9216
    unsigned* Ws1 = dsm + 9216;       // 9216
    unsigned* As0 = dsm + 18432;      // 2304
    unsigned* As1 = dsm + 20736;      // 2304
    __shared__ int srow[64];

    int tid  = threadIdx.x;
    int lane = tid & 31;
    int w    = tid >> 5;
    int lr   = lane >> 2;
    int lc   = lane & 3;
    int rt   = blockIdx.x;

    if (tid < 64) {
        int row = rt * 64 + tid;
        int b = row >> 9;
        int t = row & 511;
        srow[tid] = g_top_idx[b * K_ + (t >> 6)] * NT_ + (t & 63);
    }
    __syncthreads();

    float acc[4][4][4];
#pragma unroll
    for (int mt = 0; mt < 4; mt++)
#pragma unroll
        for (int nt = 0; nt < 4; nt++)
#pragma unroll
            for (int r = 0; r < 4; r++) acc[mt][nt][r] = 0.f;

    // ---- prologue: stage chunk 0 ----
#pragma unroll
    for (int i = 0; i < 2; i++) {
        int idx = tid + 256 * i;
        int r = idx >> 3, qv = idx & 7;
        float4 v = *(const float4*)(templates + (size_t)srow[r] * C_ + qv * 4);
        *(uint4*)(As0 + r * 36 + qv * 4) =
            make_uint4(f2tf32(v.x), f2tf32(v.y), f2tf32(v.z), f2tf32(v.w));
    }
#pragma unroll
    for (int i = 0; i < 8; i++) {
        int idx = tid + 256 * i;
        int c = idx >> 3, qv = idx & 7;
        cp_async16(Ws0 + c * 36 + qv * 4, g_w_tf32 + (size_t)c * C_ + qv * 4);
    }
    cp_commit();
    cp_wait_all();
    __syncthreads();

    for (int ch = 0; ch < 8; ch++) {
        unsigned* Asb = (ch & 1) ? As1 : As0;
        unsigned* Wsb = (ch & 1) ? Ws1 : Ws0;
        unsigned* Asn = (ch & 1) ? As0 : As1;
        unsigned* Wsn = (ch & 1) ? Ws0 : Ws1;

        float4 apf[2];
        if (ch < 7) {
            int k0n = (ch + 1) * 32;
#pragma unroll
            for (int i = 0; i < 2; i++) {
                int idx = tid + 256 * i;
                int r = idx >> 3, qv = idx & 7;
                apf[i] = *(const float4*)(templates + (size_t)srow[r] * C_ + k0n + qv * 4);
            }
#pragma unroll
            for (int i = 0; i < 8; i++) {
                int idx = tid + 256 * i;
                int c = idx >> 3, qv = idx & 7;
                cp_async16(Wsn + c * 36 + qv * 4, g_w_tf32 + (size_t)c * C_ + k0n + qv * 4);
            }
            cp_commit();
        }

#pragma unroll
        for (int ks = 0; ks < 4; ks++) {
            int k = ks * 8;
            unsigned afr[4][4], bfr[4][2];
#pragma unroll
            for (int mt = 0; mt < 4; mt++) {
                int r = mt * 16 + lr;
                afr[mt][0] = Asb[r * 36 + k + lc];
                afr[mt][1] = Asb[(r + 8) * 36 + k + lc];
                afr[mt][2] = Asb[r * 36 + k + lc + 4];
                afr[mt][3] = Asb[(r + 8) * 36 + k + lc + 4];
            }
#pragma unroll
            for (int nt = 0; nt < 4; nt++) {
                int c = w * 32 + nt * 8 + lr;
                bfr[nt][0] = Wsb[c * 36 + k + lc];
                bfr[nt][1] = Wsb[c * 36 + k + lc + 4];
            }
#pragma unroll
            for (int mt = 0; mt < 4; mt++)
#pragma unroll
                for (int nt = 0; nt < 4; nt++)
                    mma_tf32(acc[mt][nt], afr[mt], bfr[nt]);
        }

        if (ch < 7) {
#pragma unroll
            for (int i = 0; i < 2; i++) {
                int idx = tid + 256 * i;
                int r = idx >> 3, qv = idx & 7;
                *(uint4*)(Asn + r * 36 + qv * 4) =
                    make_uint4(f2tf32(apf[i].x), f2tf32(apf[i].y),
                               f2tf32(apf[i].z), f2tf32(apf[i].w));
            }
            cp_wait_all();
            __syncthreads();
        }
    }

    // ---------------- epilogue: bias + LayerNorm + gate ----------------
    float gate = 1.0f / (1.0f + expf(-gate_logit[0]));

    float bv0[4], bv1[4], gv0[4], gv1[4], be0[4], be1[4];
#pragma unroll
    for (int nt = 0; nt < 4; nt++) {
        int c = w * 32 + nt * 8 + 2 * lc;
        bv0[nt] = bias[c];  bv1[nt] = bias[c + 1];
        gv0[nt] = gamma[c]; gv1[nt] = gamma[c + 1];
        be0[nt] = beta[c];  be1[nt] = beta[c + 1];
    }

    float* sP1   = (float*)Ws0;       // [64][8]
    float* sP2   = sP1 + 512;         // [64][8]
    float* smean = sP1 + 1024;        // [64]
    float* sinv  = sP1 + 1088;        // [64]

#pragma unroll
    for (int mt = 0; mt < 4; mt++) {
        float p1a = 0.f, p2a = 0.f, p1b = 0.f, p2b = 0.f;
#pragma unroll
        for (int nt = 0; nt < 4; nt++) {
            float h0 = acc[mt][nt][0] + bv0[nt];
            float h1 = acc[mt][nt][1] + bv1[nt];
            float h2 = acc[mt][nt][2] + bv0[nt];
            float h3 = acc[mt][nt][3] + bv1[nt];
            acc[mt][nt][0] = h0; acc[mt][nt][1] = h1;
            acc[mt][nt][2] = h2; acc[mt][nt][3] = h3;
            p1a += h0 + h1;           p2a += h0 * h0 + h1 * h1;
            p1b += h2 + h3;           p2b += h2 * h2 + h3 * h3;
        }
#pragma unroll
        for (int off = 1; off <= 2; off <<= 1) {
            p1a += __shfl_xor_sync(0xffffffffu, p1a, off);
            p2a += __shfl_xor_sync(0xffffffffu, p2a, off);
            p1b += __shfl_xor_sync(0xffffffffu, p1b, off);
            p2b += __shfl_xor_sync(0xffffffffu, p2b, off);
        }
        if (lc == 0) {
            int r = mt * 16 + lr;
            sP1[r * 8 + w] = p1a;       sP2[r * 8 + w] = p2a;
            sP1[(r + 8) * 8 + w] = p1b; sP2[(r + 8) * 8 + w] = p2b;
        }
    }
    __syncthreads();

    if (tid < 64) {
        float s1 = 0.f, s2 = 0.f;
#pragma unroll
        for (int j = 0; j < 8; j++) { s1 += sP1[tid * 8 + j]; s2 += sP2[tid * 8 + j]; }
        float mean = s1 * (1.0f / C_);
        float var  = s2 * (1.0f / C_) - mean * mean;
        smean[tid] = mean;
        sinv[tid]  = rsqrtf(var + 1e-5f);
    }
    __syncthreads();

    size_t base = (size_t)rt * 64 * C_;
#pragma unroll
    for (int mt = 0; mt < 4; mt++) {
        int r0 = mt * 16 + lr;
        float m0 = smean[r0],     i0 = sinv[r0];
        float m1 = smean[r0 + 8], i1 = sinv[r0 + 8];
#pragma unroll
        for (int nt = 0; nt < 4; nt++) {
            int c = w * 32 + nt * 8 + 2 * lc;
            float2 o0, o1;
            o0.x = ((acc[mt][nt][0] - m0) * i0 * gv0[nt] + be0[nt]) * gate;
            o0.y = ((acc[mt][nt][1] - m0) * i0 * gv1[nt] + be1[nt]) * gate;
            o1.x = ((acc[mt][nt][2] - m1) * i1 * gv0[nt] + be0[nt]) * gate;
            o1.y = ((acc[mt][nt][3] - m1) * i1 * gv1[nt] + be1[nt]) * gate;
            *(float2*)(out + base + (size_t)r0 * C_ + c)       = o0;
            *(float2*)(out + base + (size_t)(r0 + 8) * C_ + c) = o1;
        }
    }

    if (rt == 0 && tid < B_)
        out[(size_t)ROWS_ * C_ + tid] = gate;
}

// ---------------------------------------------------------------------------
extern "C" void kernel_launch(void* const* d_in, const int* in_sizes, int n_in,
                              void* d_out, int out_size) {
    const float* query      = (const float*)d_in[0];
    const float* summaries  = (const float*)d_in[1];
    const float* templates  = (const float*)d_in[2];
    const float* w_proj     = (const float*)d_in[3];
    const float* b_proj     = (const float*)d_in[4];
    const float* ln_gamma   = (const float*)d_in[5];
    const float* ln_beta    = (const float*)d_in[6];
    const float* gate_logit = (const float*)d_in[7];
    float* out = (float*)d_out;

    cudaFuncSetAttribute(sims_topk_wcvt, cudaFuncAttributeMaxDynamicSharedMemorySize, 13824 * 4);
    cudaFuncSetAttribute(gemm_ln_tc, cudaFuncAttributeMaxDynamicSharedMemorySize, 23040 * 4);

    sims_topk_wcvt<<<NBLK_ + 64, 256, 13824 * 4>>>(query, summaries, w_proj);
    topk_stage2<<<B_, 256>>>();
    gemm_ln_tc<<<ROWS_ / 64, 256, 23040 * 4>>>(templates, b_proj,
                                               ln_gamma, ln_beta, gate_logit, out);
}

// round 10
// speedup vs baseline: 1.1187x; 1.1187x over previous
#include <cuda_runtime.h>
#include <cuda_bf16.h>
#include <cfloat>
#include <math.h>

// Problem constants
#define B_  64
#define C_  256
#define N_  20000
#define NT_ 64
#define K_  8
#define ROWS_ (B_ * K_ * NT_)   // 32768 output token rows
#define NBLK_ 313               // ceil(20000/64) sims blocks
#define NSLICE_ 8
#define SLICE_ 2500             // N_/NSLICE_

// Scratch (device globals; no allocation allowed)
__device__ float    g_sims[B_ * N_];
__device__ unsigned g_w_tf32[C_ * C_];
__device__ float    g_cand_v[B_ * NSLICE_ * K_];
__device__ int      g_cand_i[B_ * NSLICE_ * K_];

__device__ __forceinline__ unsigned f2tf32(float f) {
    unsigned u;
    asm("cvt.rna.tf32.f32 %0, %1;" : "=r"(u) : "f"(f));
    return u;
}

__device__ __forceinline__ void mma_tf32(float* d, const unsigned* a, const unsigned* b) {
    asm volatile(
        "mma.sync.aligned.m16n8k8.row.col.f32.tf32.tf32.f32 "
        "{%0,%1,%2,%3}, {%4,%5,%6,%7}, {%8,%9}, {%0,%1,%2,%3};"
        : "+f"(d[0]), "+f"(d[1]), "+f"(d[2]), "+f"(d[3])
        : "r"(a[0]), "r"(a[1]), "r"(a[2]), "r"(a[3]),
          "r"(b[0]), "r"(b[1]));
}

__device__ __forceinline__ void cp_async16(void* smem_dst, const void* gsrc) {
    unsigned saddr = (unsigned)__cvta_generic_to_shared(smem_dst);
    asm volatile("cp.async.cg.shared.global [%0], [%1], 16;\n"
                 :: "r"(saddr), "l"(gsrc));
}
__device__ __forceinline__ void cp_commit() {
    asm volatile("cp.async.commit_group;\n" ::: "memory");
}
__device__ __forceinline__ void cp_wait_all() {
    asm volatile("cp.async.wait_group 0;\n" ::: "memory");
}

// ---------------------------------------------------------------------------
// Kernel 1 (fused): blocks [0, NBLK_): sims (compensated tf32 MMA, fused
// summary norms) over a 64x64 tile (M=64 batch rows, N=64 bank cols).
// Blocks [NBLK_, NBLK_+64): convert W to tf32 bits.
// ---------------------------------------------------------------------------
__global__ void __launch_bounds__(256) sims_wcvt(const float* __restrict__ q,
                                                 const float* __restrict__ s,
                                                 const float* __restrict__ W) {
    if (blockIdx.x >= NBLK_) {
        int i = (blockIdx.x - NBLK_) * 256 + threadIdx.x;   // 16384 float4s
        float4 v = ((const float4*)W)[i];
        ((uint4*)g_w_tf32)[i] =
            make_uint4(f2tf32(v.x), f2tf32(v.y), f2tf32(v.z), f2tf32(v.w));
        return;
    }

    extern __shared__ unsigned dsm[];
    unsigned* Qh = dsm;            // 64*36
    unsigned* Ql = dsm + 2304;
    unsigned* Sh = dsm + 4608;
    unsigned* Sl = dsm + 6912;
    float* sinv  = (float*)dsm;    // [64], reused after k-loop

    int tid  = threadIdx.x;
    int lane = tid & 31;
    int w    = tid >> 5;
    int lr   = lane >> 2;
    int lc   = lane & 3;
    int n0   = blockIdx.x * 64;

    float acc[4][4];
#pragma unroll
    for (int mt = 0; mt < 4; mt++)
#pragma unroll
        for (int r = 0; r < 4; r++) acc[mt][r] = 0.f;

    float ssq[2] = {0.f, 0.f};

    for (int k0 = 0; k0 < C_; k0 += 32) {
        // stage Q hi/lo: 64x32 = 512 float4
#pragma unroll
        for (int i = 0; i < 2; i++) {
            int idx = tid + 256 * i;
            int r = idx >> 3, qv = idx & 7;
            float4 v = *(const float4*)(q + (size_t)r * C_ + k0 + qv * 4);
            unsigned hx = f2tf32(v.x), hy = f2tf32(v.y), hz = f2tf32(v.z), hw = f2tf32(v.w);
            *(uint4*)(Qh + r * 36 + qv * 4) = make_uint4(hx, hy, hz, hw);
            *(uint4*)(Ql + r * 36 + qv * 4) = make_uint4(
                f2tf32(v.x - __uint_as_float(hx)), f2tf32(v.y - __uint_as_float(hy)),
                f2tf32(v.z - __uint_as_float(hz)), f2tf32(v.w - __uint_as_float(hw)));
        }
        // stage S hi/lo: 64x32 = 512 float4; accumulate per-row sumsq
#pragma unroll
        for (int i = 0; i < 2; i++) {
            int idx = tid + 256 * i;
            int r = idx >> 3, qv = idx & 7;
            int n = n0 + r;
            float4 v = make_float4(0.f, 0.f, 0.f, 0.f);
            if (n < N_) v = *(const float4*)(s + (size_t)n * C_ + k0 + qv * 4);
            ssq[i] += v.x * v.x + v.y * v.y + v.z * v.z + v.w * v.w;
            unsigned hx = f2tf32(v.x), hy = f2tf32(v.y), hz = f2tf32(v.z), hw = f2tf32(v.w);
            *(uint4*)(Sh + r * 36 + qv * 4) = make_uint4(hx, hy, hz, hw);
            *(uint4*)(Sl + r * 36 + qv * 4) = make_uint4(
                f2tf32(v.x - __uint_as_float(hx)), f2tf32(v.y - __uint_as_float(hy)),
                f2tf32(v.z - __uint_as_float(hz)), f2tf32(v.w - __uint_as_float(hw)));
        }
        __syncthreads();
#pragma unroll
        for (int ks = 0; ks < 4; ks++) {
            int k = ks * 8;
            unsigned ah[4][4], al[4][4], bh[2], bl[2];
#pragma unroll
            for (int mt = 0; mt < 4; mt++) {
                int r = mt * 16 + lr;
                ah[mt][0] = Qh[r * 36 + k + lc];
                ah[mt][1] = Qh[(r + 8) * 36 + k + lc];
                ah[mt][2] = Qh[r * 36 + k + lc + 4];
                ah[mt][3] = Qh[(r + 8) * 36 + k + lc + 4];
                al[mt][0] = Ql[r * 36 + k + lc];
                al[mt][1] = Ql[(r + 8) * 36 + k + lc];
                al[mt][2] = Ql[r * 36 + k + lc + 4];
                al[mt][3] = Ql[(r + 8) * 36 + k + lc + 4];
            }
            {
                int c = w * 8 + lr;
                bh[0] = Sh[c * 36 + k + lc];
                bh[1] = Sh[c * 36 + k + lc + 4];
                bl[0] = Sl[c * 36 + k + lc];
                bl[1] = Sl[c * 36 + k + lc + 4];
            }
#pragma unroll
            for (int mt = 0; mt < 4; mt++) {
                mma_tf32(acc[mt], ah[mt], bh);
                mma_tf32(acc[mt], ah[mt], bl);
                mma_tf32(acc[mt], al[mt], bh);
            }
        }
        __syncthreads();
    }

    // finalize per-column inverse norms (reduce ssq across 8 staging threads)
#pragma unroll
    for (int i = 0; i < 2; i++) {
#pragma unroll
        for (int off = 1; off <= 4; off <<= 1)
            ssq[i] += __shfl_xor_sync(0xffffffffu, ssq[i], off);
        if ((tid & 7) == 0) {
            int r = (tid + 256 * i) >> 3;
            sinv[r] = 1.0f / fmaxf(sqrtf(ssq[i]), 1e-12f);
        }
    }
    __syncthreads();

#pragma unroll
    for (int mt = 0; mt < 4; mt++) {
        int r0 = mt * 16 + lr;     // b index (0..63)
        int cl = w * 8 + 2 * lc;
        int c = n0 + cl;
        if (c < N_) {
            float i0 = sinv[cl];
            float i1 = sinv[cl + 1];
            float2 v0 = make_float2(acc[mt][0] * i0, acc[mt][1] * i1);
            float2 v1 = make_float2(acc[mt][2] * i0, acc[mt][3] * i1);
            *(float2*)(g_sims + (size_t)r0 * N_ + c)       = v0;
            *(float2*)(g_sims + (size_t)(r0 + 8) * N_ + c) = v1;
        }
    }
}

// ---------------------------------------------------------------------------
// Kernel 2: per-(row,slice) top-8. Grid 64*8 blocks, 256 threads.
// ---------------------------------------------------------------------------
__global__ void __launch_bounds__(256) topk_stage1() {
    __shared__ float sv[2048];
    __shared__ int   si[2048];
    __shared__ float wv[8];
    __shared__ int   wi[8];
    __shared__ int   wsl[8];

    int row   = blockIdx.x >> 3;
    int slice = blockIdx.x & 7;
    int tid  = threadIdx.x;
    int lane = tid & 31;
    int w    = tid >> 5;
    const float* srow = g_sims + (size_t)row * N_;
    int nb = slice * SLICE_, ne = nb + SLICE_;

    float tv[8];
    int   ti[8];
#pragma unroll
    for (int p = 0; p < 8; p++) { tv[p] = -FLT_MAX; ti[p] = 0x7fffffff; }

    for (int n = nb + tid; n < ne; n += 256) {
        float v = srow[n];
        if (v > tv[7]) {
            tv[7] = v; ti[7] = n;
#pragma unroll
            for (int p = 7; p >= 1; p--) {
                bool sw = (tv[p] > tv[p - 1]) ||
                          (tv[p] == tv[p - 1] && ti[p] < ti[p - 1]);
                if (sw) {
                    float fv = tv[p]; tv[p] = tv[p - 1]; tv[p - 1] = fv;
                    int   fi = ti[p]; ti[p] = ti[p - 1]; ti[p - 1] = fi;
                }
            }
        }
    }
#pragma unroll
    for (int p = 0; p < 8; p++) { sv[tid * 8 + p] = tv[p]; si[tid * 8 + p] = ti[p]; }
    __syncthreads();

    for (int round = 0; round < 8; round++) {
        float bv = -FLT_MAX; int bi = 0x7fffffff; int bs = 0;
#pragma unroll
        for (int p = 0; p < 8; p++) {
            float v = sv[tid * 8 + p];
            int idx = si[tid * 8 + p];
            if (v > bv || (v == bv && idx < bi)) { bv = v; bi = idx; bs = tid * 8 + p; }
        }
#pragma unroll
        for (int off = 16; off > 0; off >>= 1) {
            float ov = __shfl_xor_sync(0xffffffffu, bv, off);
            int   oi = __shfl_xor_sync(0xffffffffu, bi, off);
            int   os = __shfl_xor_sync(0xffffffffu, bs, off);
            if (ov > bv || (ov == bv && oi < bi)) { bv = ov; bi = oi; bs = os; }
        }
        if (lane == 0) { wv[w] = bv; wi[w] = bi; wsl[w] = bs; }
        __syncthreads();
        if (tid == 0) {
            float Bv = wv[0]; int Bi = wi[0]; int Bs = wsl[0];
#pragma unroll
            for (int j = 1; j < 8; j++) {
                if (wv[j] > Bv || (wv[j] == Bv && wi[j] < Bi)) {
                    Bv = wv[j]; Bi = wi[j]; Bs = wsl[j];
                }
            }
            g_cand_v[(row * NSLICE_ + slice) * 8 + round] = Bv;
            g_cand_i[(row * NSLICE_ + slice) * 8 + round] = Bi;
            sv[Bs] = -FLT_MAX;
        }
        __syncthreads();
    }
}

// ---------------------------------------------------------------------------
// Kernel 3: gathered GEMM via tf32 mma.sync + cp.async double buffering,
// fused rank-k candidate selection (replaces topk_stage2) and fused
// bias + LayerNorm + gate. Block rt covers output rows [rt*64, rt*64+64),
// which all use template index = rank-(rt&7) of batch (rt>>3)'s candidates.
// ---------------------------------------------------------------------------
__global__ void __launch_bounds__(256, 2)
gemm_ln_tc(const float* __restrict__ templates,
           const float* __restrict__ bias,
           const float* __restrict__ gamma,
           const float* __restrict__ beta,
           const float* __restrict__ gate_logit,
           float* __restrict__ out) {
    extern __shared__ unsigned dsm[];
    unsigned* Ws0 = dsm;              // 9216
    unsigned* Ws1 = dsm + 9216;       // 9216
    unsigned* As0 = dsm + 18432;      // 2304
    unsigned* As1 = dsm + 20736;      // 2304
    __shared__ int sT;

    int tid  = threadIdx.x;
    int lane = tid & 31;
    int w    = tid >> 5;
    int lr   = lane >> 2;
    int lc   = lane & 3;
    int rt   = blockIdx.x;
    int b    = rt >> 3;
    int kk   = rt & 7;

    // ---- fused stage2: rank-kk selection over b's 64 candidates ----
    if (w == 0) {
        float v0 = g_cand_v[b * 64 + lane];
        float v1 = g_cand_v[b * 64 + 32 + lane];
        int   i0 = g_cand_i[b * 64 + lane];
        int   i1 = g_cand_i[b * 64 + 32 + lane];
        int result = 0;
        for (int round = 0; round <= kk; round++) {
            float bv; int bi; int bs;
            if (v0 > v1 || (v0 == v1 && i0 < i1)) { bv = v0; bi = i0; bs = lane; }
            else                                   { bv = v1; bi = i1; bs = 32 + lane; }
#pragma unroll
            for (int off = 16; off > 0; off >>= 1) {
                float ov = __shfl_xor_sync(0xffffffffu, bv, off);
                int   oi = __shfl_xor_sync(0xffffffffu, bi, off);
                int   os = __shfl_xor_sync(0xffffffffu, bs, off);
                if (ov > bv || (ov == bv && oi < bi)) { bv = ov; bi = oi; bs = os; }
            }
            result = bi;
            if (bs == lane)      v0 = -FLT_MAX;
            if (bs == 32 + lane) v1 = -FLT_MAX;
        }
        if (lane == 0) sT = result;
    }
    __syncthreads();
    const float* Abase = templates + (size_t)sT * NT_ * C_;   // contiguous 64 rows

    float acc[4][4][4];
#pragma unroll
    for (int mt = 0; mt < 4; mt++)
#pragma unroll
        for (int nt = 0; nt < 4; nt++)
#pragma unroll
            for (int r = 0; r < 4; r++) acc[mt][nt][r] = 0.f;

    // ---- prologue: stage chunk 0 ----
#pragma unroll
    for (int i = 0; i < 2; i++) {
        int idx = tid + 256 * i;
        int r = idx >> 3, qv = idx & 7;
        float4 v = *(const float4*)(Abase + (size_t)r * C_ + qv * 4);
        *(uint4*)(As0 + r * 36 + qv * 4) =
            make_uint4(f2tf32(v.x), f2tf32(v.y), f2tf32(v.z), f2tf32(v.w));
    }
#pragma unroll
    for (int i = 0; i < 8; i++) {
        int idx = tid + 256 * i;
        int c = idx >> 3, qv = idx & 7;
        cp_async16(Ws0 + c * 36 + qv * 4, g_w_tf32 + (size_t)c * C_ + qv * 4);
    }
    cp_commit();
    cp_wait_all();
    __syncthreads();

    for (int ch = 0; ch < 8; ch++) {
        unsigned* Asb = (ch & 1) ? As1 : As0;
        unsigned* Wsb = (ch & 1) ? Ws1 : Ws0;
        unsigned* Asn = (ch & 1) ? As0 : As1;
        unsigned* Wsn = (ch & 1) ? Ws0 : Ws1;

        float4 apf[2];
        if (ch < 7) {
            int k0n = (ch + 1) * 32;
#pragma unroll
            for (int i = 0; i < 2; i++) {
                int idx = tid + 256 * i;
                int r = idx >> 3, qv = idx & 7;
                apf[i] = *(const float4*)(Abase + (size_t)r * C_ + k0n + qv * 4);
            }
#pragma unroll
            for (int i = 0; i < 8; i++) {
                int idx = tid + 256 * i;
                int c = idx >> 3, qv = idx & 7;
                cp_async16(Wsn + c * 36 + qv * 4, g_w_tf32 + (size_t)c * C_ + k0n + qv * 4);
            }
            cp_commit();
        }

#pragma unroll
        for (int ks = 0; ks < 4; ks++) {
            int k = ks * 8;
            unsigned afr[4][4], bfr[4][2];
#pragma unroll
            for (int mt = 0; mt < 4; mt++) {
                int r = mt * 16 + lr;
                afr[mt][0] = Asb[r * 36 + k + lc];
                afr[mt][1] = Asb[(r + 8) * 36 + k + lc];
                afr[mt][2] = Asb[r * 36 + k + lc + 4];
                afr[mt][3] = Asb[(r + 8) * 36 + k + lc + 4];
            }
#pragma unroll
            for (int nt = 0; nt < 4; nt++) {
                int c = w * 32 + nt * 8 + lr;
                bfr[nt][0] = Wsb[c * 36 + k + lc];
                bfr[nt][1] = Wsb[c * 36 + k + lc + 4];
            }
#pragma unroll
            for (int mt = 0; mt < 4; mt++)
#pragma unroll
                for (int nt = 0; nt < 4; nt++)
                    mma_tf32(acc[mt][nt], afr[mt], bfr[nt]);
        }

        if (ch < 7) {
#pragma unroll
            for (int i = 0; i < 2; i++) {
                int idx = tid + 256 * i;
                int r = idx >> 3, qv = idx & 7;
                *(uint4*)(Asn + r * 36 + qv * 4) =
                    make_uint4(f2tf32(apf[i].x), f2tf32(apf[i].y),
                               f2tf32(apf[i].z), f2tf32(apf[i].w));
            }
            cp_wait_all();
            __syncthreads();
        }
    }

    // ---------------- epilogue: bias + LayerNorm + gate ----------------
    float gate = 1.0f / (1.0f + expf(-gate_logit[0]));

    float bv0[4], bv1[4], gv0[4], gv1[4], be0[4], be1[4];
#pragma unroll
    for (int nt = 0; nt < 4; nt++) {
        int c = w * 32 + nt * 8 + 2 * lc;
        bv0[nt] = bias[c];  bv1[nt] = bias[c + 1];
        gv0[nt] = gamma[c]; gv1[nt] = gamma[c + 1];
        be0[nt] = beta[c];  be1[nt] = beta[c + 1];
    }

    float* sP1   = (float*)Ws0;       // [64][8]
    float* sP2   = sP1 + 512;         // [64][8]
    float* smean = sP1 + 1024;        // [64]
    float* sinv  = sP1 + 1088;        // [64]

#pragma unroll
    for (int mt = 0; mt < 4; mt++) {
        float p1a = 0.f, p2a = 0.f, p1b = 0.f, p2b = 0.f;
#pragma unroll
        for (int nt = 0; nt < 4; nt++) {
            float h0 = acc[mt][nt][0] + bv0[nt];
            float h1 = acc[mt][nt][1] + bv1[nt];
            float h2 = acc[mt][nt][2] + bv0[nt];
            float h3 = acc[mt][nt][3] + bv1[nt];
            acc[mt][nt][0] = h0; acc[mt][nt][1] = h1;
            acc[mt][nt][2] = h2; acc[mt][nt][3] = h3;
            p1a += h0 + h1;           p2a += h0 * h0 + h1 * h1;
            p1b += h2 + h3;           p2b += h2 * h2 + h3 * h3;
        }
#pragma unroll
        for (int off = 1; off <= 2; off <<= 1) {
            p1a += __shfl_xor_sync(0xffffffffu, p1a, off);
            p2a += __shfl_xor_sync(0xffffffffu, p2a, off);
            p1b += __shfl_xor_sync(0xffffffffu, p1b, off);
            p2b += __shfl_xor_sync(0xffffffffu, p2b, off);
        }
        if (lc == 0) {
            int r = mt * 16 + lr;
            sP1[r * 8 + w] = p1a;       sP2[r * 8 + w] = p2a;
            sP1[(r + 8) * 8 + w] = p1b; sP2[(r + 8) * 8 + w] = p2b;
        }
    }
    __syncthreads();

    if (tid < 64) {
        float s1 = 0.f, s2 = 0.f;
#pragma unroll
        for (int j = 0; j < 8; j++) { s1 += sP1[tid * 8 + j]; s2 += sP2[tid * 8 + j]; }
        float mean = s1 * (1.0f / C_);
        float var  = s2 * (1.0f / C_) - mean * mean;
        smean[tid] = mean;
        sinv[tid]  = rsqrtf(var + 1e-5f);
    }
    __syncthreads();

    size_t base = (size_t)rt * 64 * C_;
#pragma unroll
    for (int mt = 0; mt < 4; mt++) {
        int r0 = mt * 16 + lr;
        float m0 = smean[r0],     i0 = sinv[r0];
        float m1 = smean[r0 + 8], i1 = sinv[r0 + 8];
#pragma unroll
        for (int nt = 0; nt < 4; nt++) {
            int c = w * 32 + nt * 8 + 2 * lc;
            float2 o0, o1;
            o0.x = ((acc[mt][nt][0] - m0) * i0 * gv0[nt] + be0[nt]) * gate;
            o0.y = ((acc[mt][nt][1] - m0) * i0 * gv1[nt] + be1[nt]) * gate;
            o1.x = ((acc[mt][nt][2] - m1) * i1 * gv0[nt] + be0[nt]) * gate;
            o1.y = ((acc[mt][nt][3] - m1) * i1 * gv1[nt] + be1[nt]) * gate;
            *(float2*)(out + base + (size_t)r0 * C_ + c)       = o0;
            *(float2*)(out + base + (size_t)(r0 + 8) * C_ + c) = o1;
        }
    }

    if (rt == 0 && tid < B_)
        out[(size_t)ROWS_ * C_ + tid] = gate;
}

// ---------------------------------------------------------------------------
extern "C" void kernel_launch(void* const* d_in, const int* in_sizes, int n_in,
                              void* d_out, int out_size) {
    const float* query      = (const float*)d_in[0];
    const float* summaries  = (const float*)d_in[1];
    const float* templates  = (const float*)d_in[2];
    const float* w_proj     = (const float*)d_in[3];
    const float* b_proj     = (const float*)d_in[4];
    const float* ln_gamma   = (const float*)d_in[5];
    const float* ln_beta    = (const float*)d_in[6];
    const float* gate_logit = (const float*)d_in[7];
    float* out = (float*)d_out;

    cudaFuncSetAttribute(gemm_ln_tc, cudaFuncAttributeMaxDynamicSharedMemorySize, 23040 * 4);

    sims_wcvt<<<NBLK_ + 64, 256, 9216 * 4>>>(query, summaries, w_proj);
    topk_stage1<<<B_ * NSLICE_, 256>>>();
    gemm_ln_tc<<<ROWS_ / 64, 256, 23040 * 4>>>(templates, b_proj,
                                               ln_gamma, ln_beta, gate_logit, out);
}